// round 9
// baseline (speedup 1.0000x reference)
#include <cuda_runtime.h>
#include <cuda_fp16.h>
#include <math.h>

#define B_    4096
#define INF   64
#define KM    16
#define SQ    32
#define HH    64
#define NMD   48
#define NH    512
#define NT    1024
#define PMAXF 8.0f

#define ROWS  32          // batch rows per block
#define RSTR  36          // xs transposed stride (32 rows + 4 pad)
#define ASTR  520         // a1 fp16 row stride (1040B: 16B-aligned, ldmatrix conflict-free)

// Scratch (no allocations allowed)
__device__ float g_tab[KM * NT];                          // G_k(p) tables
__device__ __align__(16) __half w2f_frag[NH * NH];        // w2 fp16, MMA B-fragment order

// ---------------------------------------------------------------------------
// helpers
// ---------------------------------------------------------------------------
__device__ __forceinline__ unsigned long long pack2(float lo, float hi) {
    unsigned long long r;
    asm("mov.b64 %0, {%1, %2};" : "=l"(r) : "f"(lo), "f"(hi));
    return r;
}
__device__ __forceinline__ float2 unpack2(unsigned long long v) {
    float2 r;
    asm("mov.b64 {%0, %1}, %2;" : "=f"(r.x), "=f"(r.y) : "l"(v));
    return r;
}
__device__ __forceinline__ void fma2(unsigned long long& d,
                                     unsigned long long a,
                                     unsigned long long b) {
    asm("fma.rn.f32x2 %0, %1, %2, %0;" : "+l"(d) : "l"(a), "l"(b));
}
__device__ __forceinline__ unsigned smem_u32(const void* p) {
    unsigned r;
    asm("{ .reg .u64 t; cvta.to.shared.u64 t, %1; cvt.u32.u64 %0, t; }"
        : "=r"(r) : "l"(p));
    return r;
}
__device__ __forceinline__ void ldsm_x4(unsigned& r0, unsigned& r1,
                                        unsigned& r2, unsigned& r3, unsigned addr) {
    asm volatile("ldmatrix.sync.aligned.m8n8.x4.shared.b16 {%0,%1,%2,%3}, [%4];"
                 : "=r"(r0), "=r"(r1), "=r"(r2), "=r"(r3) : "r"(addr));
}
__device__ __forceinline__ void mma_f16(float* c, const unsigned* a, const unsigned* b) {
    asm volatile(
        "mma.sync.aligned.m16n8k16.row.col.f32.f16.f16.f32 "
        "{%0,%1,%2,%3}, {%4,%5,%6,%7}, {%8,%9}, {%0,%1,%2,%3};"
        : "+f"(c[0]), "+f"(c[1]), "+f"(c[2]), "+f"(c[3])
        : "r"(a[0]), "r"(a[1]), "r"(a[2]), "r"(a[3]), "r"(b[0]), "r"(b[1]));
}

// ---------------------------------------------------------------------------
// Kernel 0: MERGED setup. Blocks [0,256): w2 -> fp16 MMA B-frag order.
// Blocks [256,384): tabulate G_k(p) (2 threads per entry, f32x2 inner).
// ---------------------------------------------------------------------------
__global__ void __launch_bounds__(256) setup_kernel(
    const float* __restrict__ w2,
    const float* __restrict__ mw1, const float* __restrict__ mb1,
    const float* __restrict__ mw2, const float* __restrict__ mb2,
    const float* __restrict__ mw3, const float* __restrict__ mb3)
{
    __shared__ float s_w2[HH * HH];
    __shared__ float s_w1[HH], s_b1[HH], s_b2[HH], s_w3[HH];

    if (blockIdx.x < 256) {
        // ---- prep: one thread per B-slot (4 halves), coalesced stores ----
        int t    = blockIdx.x * 256 + threadIdx.x;   // 65536 slots
        int nf   = t & 63;
        int lane = (t >> 6) & 31;
        int kf   = t >> 11;

        int j     = nf * 8 + (lane >> 2);
        int kbase = kf * 16 + (lane & 3) * 2;

        float v00 = __ldg(w2 + (kbase + 0) * NH + j);
        float v01 = __ldg(w2 + (kbase + 1) * NH + j);
        float v10 = __ldg(w2 + (kbase + 8) * NH + j);
        float v11 = __ldg(w2 + (kbase + 9) * NH + j);

        __half2 b0 = __floats2half2_rn(v00, v01);
        __half2 b1 = __floats2half2_rn(v10, v11);

        uint2 st;
        st.x = *(unsigned*)&b0;
        st.y = *(unsigned*)&b1;
        ((uint2*)w2f_frag)[(kf * 32 + lane) * 64 + nf] = st;
        return;
    }

    // ---- build_tab ----
    int bid = blockIdx.x - 256;
    int k  = bid >> 3;                              // 8 blocks per k
    int i  = (bid & 7) * 128 + (threadIdx.x >> 1);
    int jh = threadIdx.x & 1;

    {
        const float4* src = (const float4*)(mw2 + k * HH * HH);
        float4* dst = (float4*)s_w2;
        for (int idx = threadIdx.x; idx < HH * HH / 4; idx += 256)
            dst[idx] = src[idx];
    }
    if (threadIdx.x < HH) {
        s_w1[threadIdx.x] = mw1[k * HH + threadIdx.x];
        s_b1[threadIdx.x] = mb1[k * HH + threadIdx.x];
        s_b2[threadIdx.x] = mb2[k * HH + threadIdx.x];
        s_w3[threadIdx.x] = mw3[k * HH + threadIdx.x];
    }
    __syncthreads();

    float p = -PMAXF + (2.f * PMAXF / (NT - 1)) * (float)i;

    float h1v[HH];
#pragma unroll
    for (int h = 0; h < HH; h++)
        h1v[h] = tanhf(fmaf(p, s_w1[h], s_b1[h]));

    float z = 0.f;
#pragma unroll 2
    for (int jg = 0; jg < 8; jg++) {
        int j0 = jh * 32 + jg * 4;
        unsigned long long accA = pack2(s_b2[j0],     s_b2[j0 + 1]);
        unsigned long long accB = pack2(s_b2[j0 + 2], s_b2[j0 + 3]);
#pragma unroll
        for (int h = 0; h < HH; h++) {
            ulonglong2 w = *(const ulonglong2*)&s_w2[h * HH + j0];
            unsigned long long ad = pack2(h1v[h], h1v[h]);
            fma2(accA, w.x, ad);
            fma2(accB, w.y, ad);
        }
        float2 va = unpack2(accA);
        float2 vb = unpack2(accB);
        z = fmaf(s_w3[j0 + 0], tanhf(va.x), z);
        z = fmaf(s_w3[j0 + 1], tanhf(va.y), z);
        z = fmaf(s_w3[j0 + 2], tanhf(vb.x), z);
        z = fmaf(s_w3[j0 + 3], tanhf(vb.y), z);
    }
    z += __shfl_down_sync(0xffffffffu, z, 1, 2);
    if (jh == 0) {
        z += __ldg(mb3 + k);
        g_tab[k * NT + i] = fmaxf(z, 0.f) + log1pf(expf(-fabsf(z)));
    }
}

// ---------------------------------------------------------------------------
// Kernel 1: fused mono + layer1 + layer2(fp16 MMA) + out.
// Block = 32 rows, 1024 threads (32 warps), grid 128, 1 block/SM.
// Warp w owns cols [w*16, w*16+16): per kf: 2 ldsm.x4 + 1 LDG.128 + 4 mma.
// B prefetched 2 iterations ahead (even/odd register buffers).
// ---------------------------------------------------------------------------
__global__ void __launch_bounds__(1024) fused_kernel(
    const float* __restrict__ X,  const float* __restrict__ wlin,
    const float* __restrict__ w1, const float* __restrict__ b1,
    const float* __restrict__ b2, const float* __restrict__ w3,
    const float* __restrict__ b3, float* __restrict__ out)
{
    extern __shared__ float sm[];
    float* xs     = sm;                          // [NMD][RSTR]
    float* wpart  = xs + NMD * RSTR;             // [32][32]
    float* mono_s = wpart + 32 * 32;             // [32]
    __half* a1f   = (__half*)(mono_s + 32);      // [32][ASTR]

    const int tid  = threadIdx.x;
    const int warp = tid >> 5;
    const int lane = tid & 31;
    const int b0   = blockIdx.x * ROWS;

    // ---- stage x_nm transposed: xs[i][r] ----
    for (int idx = tid; idx < ROWS * NMD; idx += 1024) {
        int r = idx / NMD, i = idx % NMD;
        xs[i * RSTR + r] = X[(b0 + r) * INF + KM + i];
    }

    // ---- mono term: threads < 512, one (row, k) each ----
    if (tid < 512) {
        int r = tid >> 4;          // 0..31
        int k = tid & 15;
        const float scale = (float)(NT - 1) / (2.f * PMAXF);
        float x = __ldg(X + (b0 + r) * INF + k);
        const float* tk = g_tab + k * NT;
        float acc = 0.f;
#pragma unroll
        for (int s = 0; s < SQ; s++) {
            float t = (float)s * (1.f / (SQ - 1));
            float f = (x * t + PMAXF) * scale;
            f = fminf(fmaxf(f, 0.f), (float)(NT - 1) - 1e-3f);
            int i0 = (int)f;
            float fr = f - (float)i0;
            float g0 = tk[i0];
            float g1 = tk[i0 + 1];
            acc += fmaf(fr, g1 - g0, g0);
        }
        float part = acc * (1.f / SQ) * x * __ldg(wlin + k);
#pragma unroll
        for (int off = 8; off; off >>= 1)
            part += __shfl_down_sync(0xffffffffu, part, off, 16);
        if ((tid & 15) == 0) mono_s[r] = part;
    }
    __syncthreads();

    // ---- layer 1: 2 threads per col (row-halves of 16); relu -> fp16 ----
    {
        const int c  = tid >> 1;
        const int rh = tid & 1;
        unsigned long long acc[8];
#pragma unroll
        for (int rp = 0; rp < 8; rp++) acc[rp] = 0ull;

        const float* wp = w1 + c;
#pragma unroll 4
        for (int i = 0; i < NMD; i++) {
            float wv = wp[i * NH];
            unsigned long long wd = pack2(wv, wv);
            const ulonglong2* ap = (const ulonglong2*)(xs + i * RSTR + rh * 16);
#pragma unroll
            for (int q = 0; q < 4; q++) {
                ulonglong2 a = ap[q];
                fma2(acc[2 * q],     a.x, wd);
                fma2(acc[2 * q + 1], a.y, wd);
            }
        }
        float bv = b1[c];
#pragma unroll
        for (int rp = 0; rp < 8; rp++) {
            float2 v = unpack2(acc[rp]);
            a1f[(rh * 16 + 2 * rp) * ASTR + c]     = __float2half_rn(fmaxf(v.x + bv, 0.f));
            a1f[(rh * 16 + 2 * rp + 1) * ASTR + c] = __float2half_rn(fmaxf(v.y + bv, 0.f));
        }
    }
    __syncthreads();

    // ---- layer 2: fp16 MMA, warp owns 16 cols x 32 rows ----
    {
        float acc[2][2][4];
#pragma unroll
        for (int m = 0; m < 2; m++)
#pragma unroll
            for (int nf = 0; nf < 2; nf++)
#pragma unroll
                for (int e = 0; e < 4; e++) acc[m][nf][e] = 0.f;

        const unsigned a1_u = smem_u32(a1f);
        const int arow  = lane & 15;
        const int acol8 = (lane >> 4) * 8;
        const uint4* bp = (const uint4*)w2f_frag;   // index = (kf*32+lane)*32 + warp

        uint4 bqe = bp[(0 * 32 + lane) * 32 + warp];     // kf even buffer
        uint4 bqo = bp[(1 * 32 + lane) * 32 + warp];     // kf odd buffer

#pragma unroll 4
        for (int kf = 0; kf < 32; kf += 2) {
            // ---- even kf ----
            {
                unsigned bfr[2][2] = {{bqe.x, bqe.y}, {bqe.z, bqe.w}};
                if (kf + 2 < 32)
                    bqe = bp[((kf + 2) * 32 + lane) * 32 + warp];
                unsigned a[2][4];
#pragma unroll
                for (int m = 0; m < 2; m++) {
                    unsigned off = ((m * 16 + arow) * ASTR + kf * 16 + acol8) * 2;
                    ldsm_x4(a[m][0], a[m][1], a[m][2], a[m][3], a1_u + off);
                }
#pragma unroll
                for (int m = 0; m < 2; m++)
#pragma unroll
                    for (int nf = 0; nf < 2; nf++)
                        mma_f16(acc[m][nf], a[m], bfr[nf]);
            }
            // ---- odd kf ----
            {
                unsigned bfr[2][2] = {{bqo.x, bqo.y}, {bqo.z, bqo.w}};
                if (kf + 3 < 32)
                    bqo = bp[((kf + 3) * 32 + lane) * 32 + warp];
                unsigned a[2][4];
#pragma unroll
                for (int m = 0; m < 2; m++) {
                    unsigned off = ((m * 16 + arow) * ASTR + (kf + 1) * 16 + acol8) * 2;
                    ldsm_x4(a[m][0], a[m][1], a[m][2], a[m][3], a1_u + off);
                }
#pragma unroll
                for (int m = 0; m < 2; m++)
#pragma unroll
                    for (int nf = 0; nf < 2; nf++)
                        mma_f16(acc[m][nf], a[m], bfr[nf]);
            }
        }

        // epilogue: relu(acc + b2) . w3 -> per-row partials (16-col slice)
#pragma unroll
        for (int m = 0; m < 2; m++) {
            float p0 = 0.f, p1 = 0.f;
#pragma unroll
            for (int nf = 0; nf < 2; nf++) {
                int col = warp * 16 + nf * 8 + (lane & 3) * 2;
                float2 b2v = *(const float2*)(b2 + col);
                float2 w3v = *(const float2*)(w3 + col);
                p0 = fmaf(fmaxf(acc[m][nf][0] + b2v.x, 0.f), w3v.x, p0);
                p0 = fmaf(fmaxf(acc[m][nf][1] + b2v.y, 0.f), w3v.y, p0);
                p1 = fmaf(fmaxf(acc[m][nf][2] + b2v.x, 0.f), w3v.x, p1);
                p1 = fmaf(fmaxf(acc[m][nf][3] + b2v.y, 0.f), w3v.y, p1);
            }
            p0 += __shfl_xor_sync(0xffffffffu, p0, 1);
            p0 += __shfl_xor_sync(0xffffffffu, p0, 2);
            p1 += __shfl_xor_sync(0xffffffffu, p1, 1);
            p1 += __shfl_xor_sync(0xffffffffu, p1, 2);
            if ((lane & 3) == 0) {
                int r0 = m * 16 + (lane >> 2);
                wpart[warp * 32 + r0]     = p0;   // rows r0, r0+8
                wpart[warp * 32 + r0 + 8] = p1;
            }
        }
    }
    __syncthreads();

    // ---- final: sum 32 warp slices + bias + mono ----
    if (tid < ROWS) {
        float s = 0.f;
#pragma unroll
        for (int w = 0; w < 32; w++) s += wpart[w * 32 + tid];
        out[b0 + tid] = s + __ldg(b3) + mono_s[tid];
    }
}

// ---------------------------------------------------------------------------
extern "C" void kernel_launch(void* const* d_in, const int* in_sizes, int n_in,
                              void* d_out, int out_size)
{
    const float* x    = (const float*)d_in[0];
    const float* mw1  = (const float*)d_in[1];
    const float* mb1  = (const float*)d_in[2];
    const float* mw2  = (const float*)d_in[3];
    const float* mb2  = (const float*)d_in[4];
    const float* mw3  = (const float*)d_in[5];
    const float* mb3  = (const float*)d_in[6];
    const float* wlin = (const float*)d_in[7];
    const float* nw1  = (const float*)d_in[8];
    const float* nb1  = (const float*)d_in[9];
    const float* nw2  = (const float*)d_in[10];
    const float* nb2  = (const float*)d_in[11];
    const float* nw3  = (const float*)d_in[12];
    const float* nb3  = (const float*)d_in[13];
    float* out = (float*)d_out;

    // smem: xs + wpart + mono + a1f
    int smem = (NMD * RSTR + 32 * 32 + 32) * (int)sizeof(float)
             + ROWS * ASTR * (int)sizeof(__half);   // ~44.6 KB
    cudaFuncSetAttribute(fused_kernel, cudaFuncAttributeMaxDynamicSharedMemorySize, smem);

    setup_kernel<<<384, 256>>>(nw2, mw1, mb1, mw2, mb2, mw3, mb3);
    fused_kernel<<<B_ / ROWS, 1024, smem>>>(x, wlin, nw1, nb1, nb2, nw3, nb3, out);
}

// round 10
// speedup vs baseline: 1.5144x; 1.5144x over previous
#include <cuda_runtime.h>
#include <cuda_fp16.h>
#include <math.h>

#define B_    4096
#define INF   64
#define KM    16
#define SQ    32
#define HH    64
#define NMD   48
#define NH    512
#define NT    1024
#define PMAXF 8.0f

#define ROWS  32
#define RSTR  36          // xs transposed stride
#define ASTR  520         // a1 fp16 row stride (1040B, ldmatrix conflict-free)
#define NST   8           // cp.async B pipeline depth

// Scratch (no allocations allowed)
__device__ float g_tab[KM * NT];
__device__ __align__(16) __half w2f_frag[NH * NH];   // uint4 slot = kf*1024 + warp*32 + lane

// ---------------------------------------------------------------------------
// helpers
// ---------------------------------------------------------------------------
__device__ __forceinline__ unsigned long long pack2(float lo, float hi) {
    unsigned long long r;
    asm("mov.b64 %0, {%1, %2};" : "=l"(r) : "f"(lo), "f"(hi));
    return r;
}
__device__ __forceinline__ float2 unpack2(unsigned long long v) {
    float2 r;
    asm("mov.b64 {%0, %1}, %2;" : "=f"(r.x), "=f"(r.y) : "l"(v));
    return r;
}
__device__ __forceinline__ void fma2(unsigned long long& d,
                                     unsigned long long a,
                                     unsigned long long b) {
    asm("fma.rn.f32x2 %0, %1, %2, %0;" : "+l"(d) : "l"(a), "l"(b));
}
__device__ __forceinline__ unsigned smem_u32(const void* p) {
    unsigned r;
    asm("{ .reg .u64 t; cvta.to.shared.u64 t, %1; cvt.u32.u64 %0, t; }"
        : "=r"(r) : "l"(p));
    return r;
}
__device__ __forceinline__ void ldsm_x4(unsigned& r0, unsigned& r1,
                                        unsigned& r2, unsigned& r3, unsigned addr) {
    asm volatile("ldmatrix.sync.aligned.m8n8.x4.shared.b16 {%0,%1,%2,%3}, [%4];"
                 : "=r"(r0), "=r"(r1), "=r"(r2), "=r"(r3) : "r"(addr));
}
__device__ __forceinline__ void mma_f16(float* c, const unsigned* a, const unsigned* b) {
    asm volatile(
        "mma.sync.aligned.m16n8k16.row.col.f32.f16.f16.f32 "
        "{%0,%1,%2,%3}, {%4,%5,%6,%7}, {%8,%9}, {%0,%1,%2,%3};"
        : "+f"(c[0]), "+f"(c[1]), "+f"(c[2]), "+f"(c[3])
        : "r"(a[0]), "r"(a[1]), "r"(a[2]), "r"(a[3]), "r"(b[0]), "r"(b[1]));
}
__device__ __forceinline__ void cp16(unsigned saddr, const void* gptr) {
    asm volatile("cp.async.cg.shared.global [%0], [%1], 16;"
                 :: "r"(saddr), "l"(gptr) : "memory");
}
__device__ __forceinline__ void cp_commit() {
    asm volatile("cp.async.commit_group;" ::: "memory");
}
template <int N>
__device__ __forceinline__ void cp_wait() {
    asm volatile("cp.async.wait_group %0;" :: "n"(N) : "memory");
}

// ---------------------------------------------------------------------------
// Kernel 0a: w2 -> fp16, per-(kf,warp,lane) uint4 slots. 128 blocks x 256 thr.
// Slot t = kf*1024 + w*32 + lane holds {b0,b1}(nf=0), {b0,b1}(nf=1) for
// warp w's cols [w*16 + nf*8 + lane/4], k = kf*16 + (lane%4)*2 + {0,1,8,9}.
// ---------------------------------------------------------------------------
__global__ void __launch_bounds__(256) prep_kernel(const float* __restrict__ w2)
{
    int t    = blockIdx.x * 256 + threadIdx.x;   // 32768 slots
    int lane = t & 31;
    int w    = (t >> 5) & 31;
    int kf   = t >> 10;
    int kb   = kf * 16 + (lane & 3) * 2;

    uint4 st;
    unsigned* sp = (unsigned*)&st;
#pragma unroll
    for (int nf = 0; nf < 2; nf++) {
        int j = w * 16 + nf * 8 + (lane >> 2);
        float v00 = __ldg(w2 + (kb + 0) * NH + j);
        float v01 = __ldg(w2 + (kb + 1) * NH + j);
        float v10 = __ldg(w2 + (kb + 8) * NH + j);
        float v11 = __ldg(w2 + (kb + 9) * NH + j);
        __half2 b0 = __floats2half2_rn(v00, v01);
        __half2 b1 = __floats2half2_rn(v10, v11);
        sp[nf * 2 + 0] = *(unsigned*)&b0;
        sp[nf * 2 + 1] = *(unsigned*)&b1;
    }
    ((uint4*)w2f_frag)[t] = st;
}

// ---------------------------------------------------------------------------
// Kernel 0b: tabulate G_k(p). 128 blocks x 256 threads, 2 threads/entry.
// ---------------------------------------------------------------------------
__global__ void __launch_bounds__(256) build_tab_kernel(
    const float* __restrict__ mw1, const float* __restrict__ mb1,
    const float* __restrict__ mw2, const float* __restrict__ mb2,
    const float* __restrict__ mw3, const float* __restrict__ mb3)
{
    __shared__ float s_w2[HH * HH];
    __shared__ float s_w1[HH], s_b1[HH], s_b2[HH], s_w3[HH];

    int k  = blockIdx.x >> 3;
    int i  = (blockIdx.x & 7) * 128 + (threadIdx.x >> 1);
    int jh = threadIdx.x & 1;

    {
        const float4* src = (const float4*)(mw2 + k * HH * HH);
        float4* dst = (float4*)s_w2;
        for (int idx = threadIdx.x; idx < HH * HH / 4; idx += 256)
            dst[idx] = src[idx];
    }
    if (threadIdx.x < HH) {
        s_w1[threadIdx.x] = mw1[k * HH + threadIdx.x];
        s_b1[threadIdx.x] = mb1[k * HH + threadIdx.x];
        s_b2[threadIdx.x] = mb2[k * HH + threadIdx.x];
        s_w3[threadIdx.x] = mw3[k * HH + threadIdx.x];
    }
    __syncthreads();

    float p = -PMAXF + (2.f * PMAXF / (NT - 1)) * (float)i;

    float h1v[HH];
#pragma unroll
    for (int h = 0; h < HH; h++)
        h1v[h] = tanhf(fmaf(p, s_w1[h], s_b1[h]));

    float z = 0.f;
#pragma unroll 2
    for (int jg = 0; jg < 8; jg++) {
        int j0 = jh * 32 + jg * 4;
        unsigned long long accA = pack2(s_b2[j0],     s_b2[j0 + 1]);
        unsigned long long accB = pack2(s_b2[j0 + 2], s_b2[j0 + 3]);
#pragma unroll
        for (int h = 0; h < HH; h++) {
            ulonglong2 w = *(const ulonglong2*)&s_w2[h * HH + j0];
            unsigned long long ad = pack2(h1v[h], h1v[h]);
            fma2(accA, w.x, ad);
            fma2(accB, w.y, ad);
        }
        float2 va = unpack2(accA);
        float2 vb = unpack2(accB);
        z = fmaf(s_w3[j0 + 0], tanhf(va.x), z);
        z = fmaf(s_w3[j0 + 1], tanhf(va.y), z);
        z = fmaf(s_w3[j0 + 2], tanhf(vb.x), z);
        z = fmaf(s_w3[j0 + 3], tanhf(vb.y), z);
    }
    z += __shfl_down_sync(0xffffffffu, z, 1, 2);
    if (jh == 0) {
        z += __ldg(mb3 + k);
        g_tab[k * NT + i] = fmaxf(z, 0.f) + log1pf(expf(-fabsf(z)));
    }
}

// ---------------------------------------------------------------------------
// Kernel 1: fused mono + layer1 + layer2(fp16 MMA, cp.async B pipe) + out.
// 1024 threads, grid 128. Warp w owns cols [w*16,w*16+16).
// B: per-lane 16B cp.async gmem->smem, depth NST, no barriers in mainloop
// (each lane reads only its own copied bytes). A: ldsm double-buffered.
// ---------------------------------------------------------------------------
__global__ void __launch_bounds__(1024) fused_kernel(
    const float* __restrict__ X,  const float* __restrict__ wlin,
    const float* __restrict__ w1, const float* __restrict__ b1,
    const float* __restrict__ b2, const float* __restrict__ w3,
    const float* __restrict__ b3, float* __restrict__ out)
{
    extern __shared__ float sm[];
    // layout: bstage | a1f | xs | wpart | mono_s   (all 16B aligned)
    uint4*  bstage = (uint4*)sm;                       // [NST][32][32] uint4
    __half* a1f    = (__half*)(bstage + NST * 32 * 32);// [32][ASTR]
    float*  xs     = (float*)(a1f + ROWS * ASTR);      // [NMD][RSTR]
    float*  wpart  = xs + NMD * RSTR;                  // [32][32]
    float*  mono_s = wpart + 32 * 32;                  // [32]

    const int tid  = threadIdx.x;
    const int warp = tid >> 5;
    const int lane = tid & 31;
    const int b0   = blockIdx.x * ROWS;

    // ---- prime B pipeline immediately (fills during mono/layer1) ----
    const uint4* bgm = (const uint4*)w2f_frag + warp * 32 + lane;  // + kf*1024
    const unsigned bst_u = smem_u32(bstage) + (warp * 32 + lane) * 16;  // + stage*16KB
#pragma unroll
    for (int s = 0; s < NST - 1; s++) {
        cp16(bst_u + s * 16384, bgm + s * 1024);
        cp_commit();
    }

    // ---- stage x_nm transposed: xs[i][r] ----
    for (int idx = tid; idx < ROWS * NMD; idx += 1024) {
        int r = idx / NMD, i = idx % NMD;
        xs[i * RSTR + r] = X[(b0 + r) * INF + KM + i];
    }

    // ---- mono: 32 threads per row (16 k x 2 s-halves), width-32 reduce ----
    {
        int r  = tid >> 5;          // 0..31
        int k  = tid & 15;
        int sh = (tid >> 4) & 1;
        const float scale = (float)(NT - 1) / (2.f * PMAXF);
        float x = __ldg(X + (b0 + r) * INF + k);
        const float* tk = g_tab + k * NT;
        float acc = 0.f;
#pragma unroll
        for (int si = 0; si < SQ / 2; si++) {
            int s = sh * (SQ / 2) + si;
            float t = (float)s * (1.f / (SQ - 1));
            float f = (x * t + PMAXF) * scale;
            f = fminf(fmaxf(f, 0.f), (float)(NT - 1) - 1e-3f);
            int i0 = (int)f;
            float fr = f - (float)i0;
            float g0 = tk[i0];
            float g1 = tk[i0 + 1];
            acc += fmaf(fr, g1 - g0, g0);
        }
        float part = acc * (1.f / SQ) * x * __ldg(wlin + k);
#pragma unroll
        for (int off = 16; off; off >>= 1)
            part += __shfl_down_sync(0xffffffffu, part, off);
        if (lane == 0) mono_s[r] = part;
    }
    __syncthreads();

    // ---- layer 1: 2 threads per col (row-halves of 16); relu -> fp16 ----
    {
        const int c  = tid >> 1;
        const int rh = tid & 1;
        unsigned long long acc[8];
#pragma unroll
        for (int rp = 0; rp < 8; rp++) acc[rp] = 0ull;

        const float* wp = w1 + c;
#pragma unroll 4
        for (int i = 0; i < NMD; i++) {
            float wv = wp[i * NH];
            unsigned long long wd = pack2(wv, wv);
            const ulonglong2* ap = (const ulonglong2*)(xs + i * RSTR + rh * 16);
#pragma unroll
            for (int q = 0; q < 4; q++) {
                ulonglong2 a = ap[q];
                fma2(acc[2 * q],     a.x, wd);
                fma2(acc[2 * q + 1], a.y, wd);
            }
        }
        float bv = b1[c];
#pragma unroll
        for (int rp = 0; rp < 8; rp++) {
            float2 v = unpack2(acc[rp]);
            a1f[(rh * 16 + 2 * rp) * ASTR + c]     = __float2half_rn(fmaxf(v.x + bv, 0.f));
            a1f[(rh * 16 + 2 * rp + 1) * ASTR + c] = __float2half_rn(fmaxf(v.y + bv, 0.f));
        }
    }
    __syncthreads();

    // ---- layer 2: fp16 MMA; B from smem ring, A ldsm double-buffered ----
    {
        float acc[2][2][4];
#pragma unroll
        for (int m = 0; m < 2; m++)
#pragma unroll
            for (int nf = 0; nf < 2; nf++)
#pragma unroll
                for (int e = 0; e < 4; e++) acc[m][nf][e] = 0.f;

        const unsigned a1_u = smem_u32(a1f);
        const int arow  = lane & 15;
        const int acol8 = (lane >> 4) * 8;
        const uint4* bsm = bstage + warp * 32 + lane;   // + stage*1024

        unsigned a[2][2][4];   // [buf][m][frag]
#pragma unroll
        for (int m = 0; m < 2; m++) {
            unsigned off = ((m * 16 + arow) * ASTR + acol8) * 2;
            ldsm_x4(a[0][m][0], a[0][m][1], a[0][m][2], a[0][m][3], a1_u + off);
        }

        for (int kf = 0; kf < 32; kf++) {
            int cur = kf & 1, nxt = cur ^ 1;
            // issue next B stage, keep NST-1 groups ahead
            int sl = kf + NST - 1;
            if (sl < 32) cp16(bst_u + (sl & (NST - 1)) * 16384, bgm + sl * 1024);
            cp_commit();
            // prefetch next A frags
            if (kf + 1 < 32) {
#pragma unroll
                for (int m = 0; m < 2; m++) {
                    unsigned off = ((m * 16 + arow) * ASTR + (kf + 1) * 16 + acol8) * 2;
                    ldsm_x4(a[nxt][m][0], a[nxt][m][1], a[nxt][m][2], a[nxt][m][3],
                            a1_u + off);
                }
            }
            // wait for B stage kf, then consume
            cp_wait<NST - 1>();
            uint4 bq = bsm[(kf & (NST - 1)) * 1024];
            unsigned bfr[2][2] = {{bq.x, bq.y}, {bq.z, bq.w}};
#pragma unroll
            for (int m = 0; m < 2; m++)
#pragma unroll
                for (int nf = 0; nf < 2; nf++)
                    mma_f16(acc[m][nf], a[cur][m], bfr[nf]);
        }

        // epilogue: relu(acc + b2) . w3 -> per-row partials (16-col slice)
#pragma unroll
        for (int m = 0; m < 2; m++) {
            float p0 = 0.f, p1 = 0.f;
#pragma unroll
            for (int nf = 0; nf < 2; nf++) {
                int col = warp * 16 + nf * 8 + (lane & 3) * 2;
                float2 b2v = *(const float2*)(b2 + col);
                float2 w3v = *(const float2*)(w3 + col);
                p0 = fmaf(fmaxf(acc[m][nf][0] + b2v.x, 0.f), w3v.x, p0);
                p0 = fmaf(fmaxf(acc[m][nf][1] + b2v.y, 0.f), w3v.y, p0);
                p1 = fmaf(fmaxf(acc[m][nf][2] + b2v.x, 0.f), w3v.x, p1);
                p1 = fmaf(fmaxf(acc[m][nf][3] + b2v.y, 0.f), w3v.y, p1);
            }
            p0 += __shfl_xor_sync(0xffffffffu, p0, 1);
            p0 += __shfl_xor_sync(0xffffffffu, p0, 2);
            p1 += __shfl_xor_sync(0xffffffffu, p1, 1);
            p1 += __shfl_xor_sync(0xffffffffu, p1, 2);
            if ((lane & 3) == 0) {
                int r0 = m * 16 + (lane >> 2);
                wpart[warp * 32 + r0]     = p0;
                wpart[warp * 32 + r0 + 8] = p1;
            }
        }
    }
    __syncthreads();

    // ---- final: sum 32 warp slices + bias + mono ----
    if (tid < ROWS) {
        float s = 0.f;
#pragma unroll
        for (int w = 0; w < 32; w++) s += wpart[w * 32 + tid];
        out[b0 + tid] = s + __ldg(b3) + mono_s[tid];
    }
}

// ---------------------------------------------------------------------------
extern "C" void kernel_launch(void* const* d_in, const int* in_sizes, int n_in,
                              void* d_out, int out_size)
{
    const float* x    = (const float*)d_in[0];
    const float* mw1  = (const float*)d_in[1];
    const float* mb1  = (const float*)d_in[2];
    const float* mw2  = (const float*)d_in[3];
    const float* mb2  = (const float*)d_in[4];
    const float* mw3  = (const float*)d_in[5];
    const float* mb3  = (const float*)d_in[6];
    const float* wlin = (const float*)d_in[7];
    const float* nw1  = (const float*)d_in[8];
    const float* nb1  = (const float*)d_in[9];
    const float* nw2  = (const float*)d_in[10];
    const float* nb2  = (const float*)d_in[11];
    const float* nw3  = (const float*)d_in[12];
    const float* nb3  = (const float*)d_in[13];
    float* out = (float*)d_out;

    // smem: bstage(128KB) + a1f + xs + wpart + mono
    int smem = NST * 32 * 32 * 16
             + ROWS * ASTR * (int)sizeof(__half)
             + (NMD * RSTR + 32 * 32 + 32) * (int)sizeof(float);   // ~175.5 KB
    cudaFuncSetAttribute(fused_kernel, cudaFuncAttributeMaxDynamicSharedMemorySize, smem);

    prep_kernel<<<128, 256>>>(nw2);
    build_tab_kernel<<<KM * 8, 256>>>(mw1, mb1, mw2, mb2, mw3, mb3);
    fused_kernel<<<B_ / ROWS, 1024, smem>>>(x, wlin, nw1, nb1, nb2, nw3, nb3, out);
}